// round 13
// baseline (speedup 1.0000x reference)
#include <cuda_runtime.h>
#include <cuda_bf16.h>

// Problem constants (fixed by reference setup_inputs)
#define MAXN      131072
#define B_SEG     32
#define P_DIM     8
#define TF        256           // T*F = 8*32
#define BP        (B_SEG*P_DIM) // 256
#define CHUNK     64            // nodes per block in accumulate pass
#define ATH       128           // threads per accum block (thread <-> float2 of cells)
#define NSTAGE    4             // cp.async pipeline depth
#define SNODES    4             // nodes per stage (4 KB)
#define NSTAGES_TOT (CHUNK / SNODES)   // 16
#define EPS       1e-16f

// Scratch (no allocations allowed -> device globals)
__device__ float g_e[MAXN * P_DIM];   // e = exp(h)  (no max-subtract; |h| << 88)
__device__ float g_sum[BP];           // sum of e per (seg,p)

// ---------------------------------------------------------------------------
// packed f32x2 helpers (FFMA2 — only reachable via PTX fma.rn.f32x2)
// ---------------------------------------------------------------------------
__device__ __forceinline__ unsigned long long bcast2(float x) {
    unsigned long long r;
    unsigned int u = __float_as_uint(x);
    asm("mov.b64 %0, {%1, %1};" : "=l"(r) : "r"(u));
    return r;
}
__device__ __forceinline__ unsigned long long pack2f(float2 v) {
    unsigned long long r;
    asm("mov.b64 %0, {%1, %2};" : "=l"(r) : "r"(__float_as_uint(v.x)), "r"(__float_as_uint(v.y)));
    return r;
}
__device__ __forceinline__ void fma2(unsigned long long& acc,
                                     unsigned long long a, unsigned long long b) {
    asm("fma.rn.f32x2 %0, %1, %2, %3;" : "=l"(acc) : "l"(a), "l"(b), "l"(acc));
}
__device__ __forceinline__ unsigned int smem_u32(const void* p) {
    unsigned int a;
    asm("{ .reg .u64 t; cvta.to.shared.u64 t, %1; cvt.u32.u64 %0, t; }" : "=r"(a) : "l"(p));
    return a;
}
__device__ __forceinline__ void cp_async16(unsigned int dst, const void* src) {
    asm volatile("cp.async.cg.shared.global [%0], [%1], 16;" :: "r"(dst), "l"(src));
}
__device__ __forceinline__ void cp_commit() {
    asm volatile("cp.async.commit_group;" ::: "memory");
}
__device__ __forceinline__ void cp_wait2() {
    asm volatile("cp.async.wait_group 2;" ::: "memory");
}

// ---------------------------------------------------------------------------
// K1 (fused): zero out; h = elu(pos@W1+b1)@W2+b2 ; e = exp(h) ; segment sum
// ---------------------------------------------------------------------------
__global__ void __launch_bounds__(256) mlp_exp_sum_kernel(
    const float* __restrict__ pos, const int* __restrict__ seg,
    const float* __restrict__ W1, const float* __restrict__ b1,
    const float* __restrict__ W2, const float* __restrict__ b2,
    float* __restrict__ out, int out_size, int N)
{
    __shared__ float sW1[24], sb1[8], sW2[64], sb2[8];
    int tid = threadIdx.x;

    // zero the output buffer (grid covers out_size at this problem scale)
    int gstride = gridDim.x * blockDim.x;
    for (int i = blockIdx.x * blockDim.x + tid; i < out_size; i += gstride)
        out[i] = 0.0f;

    if (tid < 24) sW1[tid] = __ldg(&W1[tid]);
    if (tid < 8)  { sb1[tid] = __ldg(&b1[tid]); sb2[tid] = __ldg(&b2[tid]); }
    if (tid < 64) sW2[tid] = __ldg(&W2[tid]);
    __syncthreads();

    int n = blockIdx.x * 256 + tid;
    unsigned act = __ballot_sync(0xffffffffu, n < N);
    if (n >= N) return;

    int s = __ldg(&seg[n]);
    float p0 = __ldg(&pos[3*n+0]), p1 = __ldg(&pos[3*n+1]), p2 = __ldg(&pos[3*n+2]);
    float hid[8];
#pragma unroll
    for (int j = 0; j < 8; j++) {
        float v = fmaf(p0, sW1[j], fmaf(p1, sW1[8+j], fmaf(p2, sW1[16+j], sb1[j])));
        hid[j] = (v > 0.0f) ? v : (__expf(v) - 1.0f);   // fast ELU (MUFU)
    }
    float e[8];
#pragma unroll
    for (int p = 0; p < 8; p++) {
        float v = sb2[p];
#pragma unroll
        for (int j = 0; j < 8; j++) v = fmaf(hid[j], sW2[j*8+p], v);
        e[p] = __expf(v);                // TAU = 1; |v| << 88, no max-subtract
    }
    float4* dst = (float4*)&g_e[(size_t)8*n];
    dst[0] = make_float4(e[0], e[1], e[2], e[3]);
    dst[1] = make_float4(e[4], e[5], e[6], e[7]);

    int s0 = __shfl_sync(act, s, 0);
    bool uniform_full = (act == 0xffffffffu) && __all_sync(act, s == s0);
    if (uniform_full) {
#pragma unroll
        for (int p = 0; p < 8; p++) {
#pragma unroll
            for (int off = 16; off; off >>= 1)
                e[p] += __shfl_xor_sync(0xffffffffu, e[p], off);
        }
        if ((tid & 31) == 0) {
#pragma unroll
            for (int p = 0; p < 8; p++)
                atomicAdd(&g_sum[s*8+p], e[p]);
        }
    } else {
#pragma unroll
        for (int p = 0; p < 8; p++)
            atomicAdd(&g_sum[s*8+p], e[p]);
    }
}

// ---------------------------------------------------------------------------
// K2: out[b,t,p,f] += x[n,t,f] * w[n,p]     (heavy, HBM-bound pass)
// 128-thread blocks; thread tid owns cells (2*tid, 2*tid+1).
// Fast path: x staged through smem via a 4-deep cp.async pipeline
// (4 nodes / 4 KB per stage) -> LDG latency decoupled from the FFMA2 stream.
// ---------------------------------------------------------------------------
__device__ __forceinline__ void flush_acc2c(float* __restrict__ out, int s,
                                            const unsigned long long acc2[8], int tid)
{
    int c  = 2 * tid;
    int bo = s * 2048 + ((c >> 5) << 8) + (c & 31);
#pragma unroll
    for (int p = 0; p < 8; p++) {
        unsigned long long a = acc2[p];
        atomicAdd(&out[bo + p*32 + 0], __uint_as_float((unsigned int)a));
        atomicAdd(&out[bo + p*32 + 1], __uint_as_float((unsigned int)(a >> 32)));
    }
}

__device__ __forceinline__ void node_fma2(unsigned long long acc2[8],
                                          unsigned long long xv2,
                                          const unsigned long long* __restrict__ wn)
{
    ulonglong2 w01 = *(const ulonglong2*)&wn[0];
    ulonglong2 w23 = *(const ulonglong2*)&wn[2];
    ulonglong2 w45 = *(const ulonglong2*)&wn[4];
    ulonglong2 w67 = *(const ulonglong2*)&wn[6];
    fma2(acc2[0], xv2, w01.x);
    fma2(acc2[1], xv2, w01.y);
    fma2(acc2[2], xv2, w23.x);
    fma2(acc2[3], xv2, w23.y);
    fma2(acc2[4], xv2, w45.x);
    fma2(acc2[5], xv2, w45.y);
    fma2(acc2[6], xv2, w67.x);
    fma2(acc2[7], xv2, w67.y);
}

__global__ void __launch_bounds__(ATH) accum_kernel(
    const float* __restrict__ x, const int* __restrict__ seg,
    float* __restrict__ out, int N)
{
    __shared__ float ssum[BP];
    __shared__ int   sseg[CHUNK];
    __shared__ __align__(16) unsigned long long sw2[CHUNK * 8];     // w broadcast pairs
    __shared__ __align__(16) float sx[NSTAGE * SNODES * TF];        // x staging ring (16 KB)

    int tid  = threadIdx.x;
    int base = blockIdx.x * CHUNK;
    int cnt  = min(CHUNK, N - base);

#pragma unroll
    for (int k = 0; k < BP / ATH; k++)
        ssum[tid + ATH*k] = g_sum[tid + ATH*k];
    __syncthreads();

    // w for this chunk -> shared, pre-duplicated into f32x2 broadcast form
    if (tid < cnt) {
        int n = base + tid;
        int s = __ldg(&seg[n]);
        sseg[tid] = s;
        const float4* pe = (const float4*)&g_e[(size_t)8*n];
        float4 a = pe[0], b = pe[1];
        float e[8] = {a.x, a.y, a.z, a.w, b.x, b.y, b.z, b.w};
#pragma unroll
        for (int p = 0; p < 8; p++)
            sw2[8*tid + p] = bcast2(e[p] / (ssum[s*8+p] + EPS));
    }
    __syncthreads();

    unsigned long long acc2[8];
#pragma unroll
    for (int k = 0; k < 8; k++) acc2[k] = 0ull;

    if (cnt == CHUNK && sseg[0] == sseg[CHUNK-1]) {
        // ---- fast path: cp.async pipelined stream over 16 stages of 4 nodes ----
        const char* gsrc = (const char*)(x + (size_t)base * TF);
        unsigned int sx_base = smem_u32(sx);
        int off0 = tid * 16;                    // two 16B chunks per thread per stage

        // prime NSTAGE-1 stages
#pragma unroll
        for (int s = 0; s < NSTAGE - 1; s++) {
            unsigned int db = sx_base + s * (SNODES*TF*4);
            const char* gs = gsrc + s * (SNODES*TF*4);
            cp_async16(db + off0,        gs + off0);
            cp_async16(db + off0 + 2048, gs + off0 + 2048);
            cp_commit();
        }

        for (int s = 0; s < NSTAGES_TOT; s++) {
            cp_wait2();                          // oldest pending stage complete
            __syncthreads();                     // all threads past previous consume
            int pf = s + NSTAGE - 1;
            if (pf < NSTAGES_TOT) {              // prefetch into the freed buffer
                unsigned int db = sx_base + (pf & (NSTAGE-1)) * (SNODES*TF*4);
                const char* gs = gsrc + pf * (SNODES*TF*4);
                cp_async16(db + off0,        gs + off0);
                cp_async16(db + off0 + 2048, gs + off0 + 2048);
            }
            cp_commit();                         // one group per iteration (may be empty)
            const float* sb = sx + (s & (NSTAGE-1)) * (SNODES*TF);
#pragma unroll
            for (int j = 0; j < SNODES; j++) {
                unsigned long long xv = pack2f(*(const float2*)&sb[j*TF + 2*tid]);
                node_fma2(acc2, xv, &sw2[8*(s*SNODES + j)]);
            }
        }
        flush_acc2c(out, sseg[0], acc2, tid);
    } else {
        // ---- slow path: direct LDG, per-thread segment tracking ----
        const float2* xp = (const float2*)(x + (size_t)base * TF) + tid;
        int cur = sseg[0];
        for (int i = 0; i < cnt; i++) {
            int s = sseg[i];
            if (s != cur) {
                flush_acc2c(out, cur, acc2, tid);
#pragma unroll
                for (int k = 0; k < 8; k++) acc2[k] = 0ull;
                cur = s;
            }
            unsigned long long xv = pack2f(__ldg(&xp[i * (TF/2)]));
            node_fma2(acc2, xv, &sw2[8*i]);
        }
        flush_acc2c(out, cur, acc2, tid);
    }
}

// ---------------------------------------------------------------------------
extern "C" void kernel_launch(void* const* d_in, const int* in_sizes, int n_in,
                              void* d_out, int out_size)
{
    const float* pos = (const float*)d_in[0];
    const float* x   = (const float*)d_in[1];
    const int*   seg = (const int*)  d_in[2];
    const float* W1  = (const float*)d_in[3];
    const float* b1  = (const float*)d_in[4];
    const float* W2  = (const float*)d_in[5];
    const float* b2  = (const float*)d_in[6];
    float* out = (float*)d_out;

    int N = in_sizes[2];               // seg has one entry per node

    // zero g_sum via a graph memset node (cheaper than a 1-block kernel launch)
    void* sum_ptr = nullptr;
    cudaGetSymbolAddress(&sum_ptr, g_sum);
    cudaMemsetAsync(sum_ptr, 0, BP * sizeof(float));

    mlp_exp_sum_kernel<<<(N + 255) / 256, 256>>>(pos, seg, W1, b1, W2, b2,
                                                 out, out_size, N);
    accum_kernel<<<(N + CHUNK - 1) / CHUNK, ATH>>>(x, seg, out, N);
}

// round 16
// speedup vs baseline: 1.0686x; 1.0686x over previous
#include <cuda_runtime.h>
#include <cuda_bf16.h>

// Problem constants (fixed by reference setup_inputs)
#define MAXN      131072
#define B_SEG     32
#define P_DIM     8
#define TF        256           // T*F = 8*32
#define BP        (B_SEG*P_DIM) // 256
#define CHUNK     64            // nodes per block in accumulate pass
#define ATH       128           // threads per accum block (thread <-> float2 of cells)
#define NB        8             // nodes per load batch (8 LDG.64 in flight per thread)
#define EPS       1e-16f

// Scratch (no allocations allowed -> device globals)
__device__ float g_e[MAXN * P_DIM];   // e = exp(h)  (no max-subtract; |h| << 88)
__device__ float g_sum[BP];           // sum of e per (seg,p)

// ---------------------------------------------------------------------------
// packed f32x2 helpers (FFMA2 — only reachable via PTX fma.rn.f32x2)
// ---------------------------------------------------------------------------
__device__ __forceinline__ unsigned long long bcast2(float x) {
    unsigned long long r;
    unsigned int u = __float_as_uint(x);
    asm("mov.b64 %0, {%1, %1};" : "=l"(r) : "r"(u));
    return r;
}
__device__ __forceinline__ unsigned long long pack2f(float2 v) {
    unsigned long long r;
    asm("mov.b64 %0, {%1, %2};" : "=l"(r) : "r"(__float_as_uint(v.x)), "r"(__float_as_uint(v.y)));
    return r;
}
__device__ __forceinline__ void fma2(unsigned long long& acc,
                                     unsigned long long a, unsigned long long b) {
    asm("fma.rn.f32x2 %0, %1, %2, %3;" : "=l"(acc) : "l"(a), "l"(b), "l"(acc));
}

// ---------------------------------------------------------------------------
// K1 (fused): zero out; h = elu(pos@W1+b1)@W2+b2 ; e = exp(h) ; segment sum
// ---------------------------------------------------------------------------
__global__ void __launch_bounds__(256) mlp_exp_sum_kernel(
    const float* __restrict__ pos, const int* __restrict__ seg,
    const float* __restrict__ W1, const float* __restrict__ b1,
    const float* __restrict__ W2, const float* __restrict__ b2,
    float* __restrict__ out, int out_size, int N)
{
    __shared__ float sW1[24], sb1[8], sW2[64], sb2[8];
    int tid = threadIdx.x;

    // zero the output buffer (grid covers out_size at this problem scale)
    int gstride = gridDim.x * blockDim.x;
    for (int i = blockIdx.x * blockDim.x + tid; i < out_size; i += gstride)
        out[i] = 0.0f;

    if (tid < 24) sW1[tid] = __ldg(&W1[tid]);
    if (tid < 8)  { sb1[tid] = __ldg(&b1[tid]); sb2[tid] = __ldg(&b2[tid]); }
    if (tid < 64) sW2[tid] = __ldg(&W2[tid]);
    __syncthreads();

    int n = blockIdx.x * 256 + tid;
    unsigned act = __ballot_sync(0xffffffffu, n < N);
    if (n >= N) return;

    int s = __ldg(&seg[n]);
    float p0 = __ldg(&pos[3*n+0]), p1 = __ldg(&pos[3*n+1]), p2 = __ldg(&pos[3*n+2]);
    float hid[8];
#pragma unroll
    for (int j = 0; j < 8; j++) {
        float v = fmaf(p0, sW1[j], fmaf(p1, sW1[8+j], fmaf(p2, sW1[16+j], sb1[j])));
        hid[j] = (v > 0.0f) ? v : (__expf(v) - 1.0f);   // fast ELU (MUFU)
    }
    float e[8];
#pragma unroll
    for (int p = 0; p < 8; p++) {
        float v = sb2[p];
#pragma unroll
        for (int j = 0; j < 8; j++) v = fmaf(hid[j], sW2[j*8+p], v);
        e[p] = __expf(v);                // TAU = 1; |v| << 88, no max-subtract
    }
    float4* dst = (float4*)&g_e[(size_t)8*n];
    dst[0] = make_float4(e[0], e[1], e[2], e[3]);
    dst[1] = make_float4(e[4], e[5], e[6], e[7]);

    int s0 = __shfl_sync(act, s, 0);
    bool uniform_full = (act == 0xffffffffu) && __all_sync(act, s == s0);
    if (uniform_full) {
#pragma unroll
        for (int p = 0; p < 8; p++) {
#pragma unroll
            for (int off = 16; off; off >>= 1)
                e[p] += __shfl_xor_sync(0xffffffffu, e[p], off);
        }
        if ((tid & 31) == 0) {
#pragma unroll
            for (int p = 0; p < 8; p++)
                atomicAdd(&g_sum[s*8+p], e[p]);
        }
    } else {
#pragma unroll
        for (int p = 0; p < 8; p++)
            atomicAdd(&g_sum[s*8+p], e[p]);
    }
}

// ---------------------------------------------------------------------------
// K2: out[b,t,p,f] += x[n,t,f] * w[n,p]     (heavy, HBM-bound pass)
// 128-thread blocks; thread tid owns cells (2*tid, 2*tid+1) -> LDG.64 on x.
// 8-node front-batched loads (64 B/thread in flight); FFMA2 accumulators.
// ---------------------------------------------------------------------------
__device__ __forceinline__ void flush_acc2c(float* __restrict__ out, int s,
                                            const unsigned long long acc2[8], int tid)
{
    int c  = 2 * tid;
    int bo = s * 2048 + ((c >> 5) << 8) + (c & 31);
#pragma unroll
    for (int p = 0; p < 8; p++) {
        unsigned long long a = acc2[p];
        atomicAdd(&out[bo + p*32 + 0], __uint_as_float((unsigned int)a));
        atomicAdd(&out[bo + p*32 + 1], __uint_as_float((unsigned int)(a >> 32)));
    }
}

__device__ __forceinline__ void node_fma2(unsigned long long acc2[8],
                                          unsigned long long xv2,
                                          const unsigned long long* __restrict__ wn)
{
    ulonglong2 w01 = *(const ulonglong2*)&wn[0];
    ulonglong2 w23 = *(const ulonglong2*)&wn[2];
    ulonglong2 w45 = *(const ulonglong2*)&wn[4];
    ulonglong2 w67 = *(const ulonglong2*)&wn[6];
    fma2(acc2[0], xv2, w01.x);
    fma2(acc2[1], xv2, w01.y);
    fma2(acc2[2], xv2, w23.x);
    fma2(acc2[3], xv2, w23.y);
    fma2(acc2[4], xv2, w45.x);
    fma2(acc2[5], xv2, w45.y);
    fma2(acc2[6], xv2, w67.x);
    fma2(acc2[7], xv2, w67.y);
}

__global__ void __launch_bounds__(ATH, 8) accum_kernel(
    const float* __restrict__ x, const int* __restrict__ seg,
    float* __restrict__ out, int N)
{
    __shared__ float ssum[BP];
    __shared__ int   sseg[CHUNK];
    __shared__ __align__(16) unsigned long long sw2[CHUNK * 8];  // w broadcast pairs

    int tid  = threadIdx.x;
    int base = blockIdx.x * CHUNK;
    int cnt  = min(CHUNK, N - base);

#pragma unroll
    for (int k = 0; k < BP / ATH; k++)
        ssum[tid + ATH*k] = g_sum[tid + ATH*k];
    __syncthreads();

    // w for this chunk -> shared, pre-duplicated into f32x2 broadcast form
    if (tid < cnt) {
        int n = base + tid;
        int s = __ldg(&seg[n]);
        sseg[tid] = s;
        const float4* pe = (const float4*)&g_e[(size_t)8*n];
        float4 a = pe[0], b = pe[1];
        float e[8] = {a.x, a.y, a.z, a.w, b.x, b.y, b.z, b.w};
#pragma unroll
        for (int p = 0; p < 8; p++)
            sw2[8*tid + p] = bcast2(e[p] / (ssum[s*8+p] + EPS));
    }
    __syncthreads();

    // thread's float2 lane within each node row (node i at xp + i*128)
    const float2* xp = (const float2*)(x + (size_t)base * TF) + tid;
    unsigned long long acc2[8];
#pragma unroll
    for (int k = 0; k < 8; k++) acc2[k] = 0ull;

    if (cnt == CHUNK && sseg[0] == sseg[CHUNK-1]) {
        // fast path: full chunk, single segment; 8-node front-batched LDG.64
#pragma unroll
        for (int ib = 0; ib < CHUNK / NB; ib++) {
            unsigned long long xv[NB];
#pragma unroll
            for (int j = 0; j < NB; j++)
                xv[j] = pack2f(__ldg(&xp[(ib*NB + j) * (TF/2)]));
#pragma unroll
            for (int j = 0; j < NB; j++)
                node_fma2(acc2, xv[j], &sw2[8*(ib*NB + j)]);
        }
        flush_acc2c(out, sseg[0], acc2, tid);
    } else {
        int cur = sseg[0];
        for (int i = 0; i < cnt; i++) {
            int s = sseg[i];
            if (s != cur) {           // boundary (uniform across block)
                flush_acc2c(out, cur, acc2, tid);
#pragma unroll
                for (int k = 0; k < 8; k++) acc2[k] = 0ull;
                cur = s;
            }
            unsigned long long xv = pack2f(__ldg(&xp[i * (TF/2)]));
            node_fma2(acc2, xv, &sw2[8*i]);
        }
        flush_acc2c(out, cur, acc2, tid);
    }
}

// ---------------------------------------------------------------------------
extern "C" void kernel_launch(void* const* d_in, const int* in_sizes, int n_in,
                              void* d_out, int out_size)
{
    const float* pos = (const float*)d_in[0];
    const float* x   = (const float*)d_in[1];
    const int*   seg = (const int*)  d_in[2];
    const float* W1  = (const float*)d_in[3];
    const float* b1  = (const float*)d_in[4];
    const float* W2  = (const float*)d_in[5];
    const float* b2  = (const float*)d_in[6];
    float* out = (float*)d_out;

    int N = in_sizes[2];               // seg has one entry per node

    // zero g_sum via a graph memset node (cheaper than a 1-block kernel launch)
    void* sum_ptr = nullptr;
    cudaGetSymbolAddress(&sum_ptr, g_sum);
    cudaMemsetAsync(sum_ptr, 0, BP * sizeof(float));

    mlp_exp_sum_kernel<<<(N + 255) / 256, 256>>>(pos, seg, W1, b1, W2, b2,
                                                 out, out_size, N);
    accum_kernel<<<(N + CHUNK - 1) / CHUNK, ATH>>>(x, seg, out, N);
}

// round 17
// speedup vs baseline: 1.2199x; 1.1416x over previous
#include <cuda_runtime.h>
#include <cuda_bf16.h>

// Problem constants (fixed by reference setup_inputs)
#define MAXN      131072
#define B_SEG     32
#define P_DIM     8
#define TF        256           // T*F = 8*32
#define BP        (B_SEG*P_DIM) // 256
#define CHUNK     32            // nodes per block in accumulate pass (backlog!)
#define ATH       128           // threads per accum block (thread <-> float2 of cells)
#define NB        4             // nodes per load batch (known-best from R11)
#define EPS       1e-16f

// Scratch (no allocations allowed -> device globals)
__device__ float g_e[MAXN * P_DIM];   // e = exp(h)  (no max-subtract; |h| << 88)
__device__ float g_sum[BP];           // sum of e per (seg,p)

// ---------------------------------------------------------------------------
// packed f32x2 helpers (FFMA2 — only reachable via PTX fma.rn.f32x2)
// ---------------------------------------------------------------------------
__device__ __forceinline__ unsigned long long bcast2(float x) {
    unsigned long long r;
    unsigned int u = __float_as_uint(x);
    asm("mov.b64 %0, {%1, %1};" : "=l"(r) : "r"(u));
    return r;
}
__device__ __forceinline__ unsigned long long pack2f(float2 v) {
    unsigned long long r;
    asm("mov.b64 %0, {%1, %2};" : "=l"(r) : "r"(__float_as_uint(v.x)), "r"(__float_as_uint(v.y)));
    return r;
}
__device__ __forceinline__ void fma2(unsigned long long& acc,
                                     unsigned long long a, unsigned long long b) {
    asm("fma.rn.f32x2 %0, %1, %2, %3;" : "=l"(acc) : "l"(a), "l"(b), "l"(acc));
}

// ---------------------------------------------------------------------------
// K1 (fused): zero out; h = elu(pos@W1+b1)@W2+b2 ; e = exp(h) ; segment sum
// ---------------------------------------------------------------------------
__global__ void __launch_bounds__(256) mlp_exp_sum_kernel(
    const float* __restrict__ pos, const int* __restrict__ seg,
    const float* __restrict__ W1, const float* __restrict__ b1,
    const float* __restrict__ W2, const float* __restrict__ b2,
    float* __restrict__ out, int out_size, int N)
{
    __shared__ float sW1[24], sb1[8], sW2[64], sb2[8];
    int tid = threadIdx.x;

    // zero the output buffer (grid covers out_size at this problem scale)
    int gstride = gridDim.x * blockDim.x;
    for (int i = blockIdx.x * blockDim.x + tid; i < out_size; i += gstride)
        out[i] = 0.0f;

    if (tid < 24) sW1[tid] = __ldg(&W1[tid]);
    if (tid < 8)  { sb1[tid] = __ldg(&b1[tid]); sb2[tid] = __ldg(&b2[tid]); }
    if (tid < 64) sW2[tid] = __ldg(&W2[tid]);
    __syncthreads();

    int n = blockIdx.x * 256 + tid;
    unsigned act = __ballot_sync(0xffffffffu, n < N);
    if (n >= N) return;

    int s = __ldg(&seg[n]);
    float p0 = __ldg(&pos[3*n+0]), p1 = __ldg(&pos[3*n+1]), p2 = __ldg(&pos[3*n+2]);
    float hid[8];
#pragma unroll
    for (int j = 0; j < 8; j++) {
        float v = fmaf(p0, sW1[j], fmaf(p1, sW1[8+j], fmaf(p2, sW1[16+j], sb1[j])));
        hid[j] = (v > 0.0f) ? v : (__expf(v) - 1.0f);   // fast ELU (MUFU)
    }
    float e[8];
#pragma unroll
    for (int p = 0; p < 8; p++) {
        float v = sb2[p];
#pragma unroll
        for (int j = 0; j < 8; j++) v = fmaf(hid[j], sW2[j*8+p], v);
        e[p] = __expf(v);                // TAU = 1; |v| << 88, no max-subtract
    }
    float4* dst = (float4*)&g_e[(size_t)8*n];
    dst[0] = make_float4(e[0], e[1], e[2], e[3]);
    dst[1] = make_float4(e[4], e[5], e[6], e[7]);

    int s0 = __shfl_sync(act, s, 0);
    bool uniform_full = (act == 0xffffffffu) && __all_sync(act, s == s0);
    if (uniform_full) {
#pragma unroll
        for (int p = 0; p < 8; p++) {
#pragma unroll
            for (int off = 16; off; off >>= 1)
                e[p] += __shfl_xor_sync(0xffffffffu, e[p], off);
        }
        if ((tid & 31) == 0) {
#pragma unroll
            for (int p = 0; p < 8; p++)
                atomicAdd(&g_sum[s*8+p], e[p]);
        }
    } else {
#pragma unroll
        for (int p = 0; p < 8; p++)
            atomicAdd(&g_sum[s*8+p], e[p]);
    }
}

// ---------------------------------------------------------------------------
// K2: out[b,t,p,f] += x[n,t,f] * w[n,p]     (heavy, HBM-bound pass)
// 128-thread blocks; thread tid owns cells (2*tid, 2*tid+1) -> LDG.64 on x.
// CHUNK=32 -> 3125 blocks: deep backlog hides block prologue/tail latency.
// ---------------------------------------------------------------------------
__device__ __forceinline__ void flush_acc2c(float* __restrict__ out, int s,
                                            const unsigned long long acc2[8], int tid)
{
    int c  = 2 * tid;
    int bo = s * 2048 + ((c >> 5) << 8) + (c & 31);
#pragma unroll
    for (int p = 0; p < 8; p++) {
        unsigned long long a = acc2[p];
        atomicAdd(&out[bo + p*32 + 0], __uint_as_float((unsigned int)a));
        atomicAdd(&out[bo + p*32 + 1], __uint_as_float((unsigned int)(a >> 32)));
    }
}

__device__ __forceinline__ void node_fma2(unsigned long long acc2[8],
                                          unsigned long long xv2,
                                          const unsigned long long* __restrict__ wn)
{
    ulonglong2 w01 = *(const ulonglong2*)&wn[0];
    ulonglong2 w23 = *(const ulonglong2*)&wn[2];
    ulonglong2 w45 = *(const ulonglong2*)&wn[4];
    ulonglong2 w67 = *(const ulonglong2*)&wn[6];
    fma2(acc2[0], xv2, w01.x);
    fma2(acc2[1], xv2, w01.y);
    fma2(acc2[2], xv2, w23.x);
    fma2(acc2[3], xv2, w23.y);
    fma2(acc2[4], xv2, w45.x);
    fma2(acc2[5], xv2, w45.y);
    fma2(acc2[6], xv2, w67.x);
    fma2(acc2[7], xv2, w67.y);
}

__global__ void __launch_bounds__(ATH, 12) accum_kernel(
    const float* __restrict__ x, const int* __restrict__ seg,
    float* __restrict__ out, int N)
{
    __shared__ int sseg[CHUNK];
    __shared__ __align__(16) unsigned long long sw2[CHUNK * 8];  // w broadcast pairs

    int tid  = threadIdx.x;
    int base = blockIdx.x * CHUNK;
    int cnt  = min(CHUNK, N - base);

    // w for this chunk -> shared; sums read directly (1KB table, L1/L2 broadcast)
    if (tid < cnt) {
        int n = base + tid;
        int s = __ldg(&seg[n]);
        sseg[tid] = s;
        const float4* pe = (const float4*)&g_e[(size_t)8*n];
        float4 a = pe[0], b = pe[1];
        float e[8] = {a.x, a.y, a.z, a.w, b.x, b.y, b.z, b.w};
#pragma unroll
        for (int p = 0; p < 8; p++)
            sw2[8*tid + p] = bcast2(e[p] / (g_sum[s*8+p] + EPS));
    }
    __syncthreads();

    // thread's float2 lane within each node row (node i at xp + i*128)
    const float2* xp = (const float2*)(x + (size_t)base * TF) + tid;
    unsigned long long acc2[8];
#pragma unroll
    for (int k = 0; k < 8; k++) acc2[k] = 0ull;

    if (cnt == CHUNK && sseg[0] == sseg[CHUNK-1]) {
        // fast path: full chunk, single segment; NB-node front-batched LDG.64
#pragma unroll
        for (int ib = 0; ib < CHUNK / NB; ib++) {
            unsigned long long xv[NB];
#pragma unroll
            for (int j = 0; j < NB; j++)
                xv[j] = pack2f(__ldg(&xp[(ib*NB + j) * (TF/2)]));
#pragma unroll
            for (int j = 0; j < NB; j++)
                node_fma2(acc2, xv[j], &sw2[8*(ib*NB + j)]);
        }
        flush_acc2c(out, sseg[0], acc2, tid);
    } else {
        int cur = sseg[0];
        for (int i = 0; i < cnt; i++) {
            int s = sseg[i];
            if (s != cur) {           // boundary (uniform across block)
                flush_acc2c(out, cur, acc2, tid);
#pragma unroll
                for (int k = 0; k < 8; k++) acc2[k] = 0ull;
                cur = s;
            }
            unsigned long long xv = pack2f(__ldg(&xp[i * (TF/2)]));
            node_fma2(acc2, xv, &sw2[8*i]);
        }
        flush_acc2c(out, cur, acc2, tid);
    }
}

// ---------------------------------------------------------------------------
extern "C" void kernel_launch(void* const* d_in, const int* in_sizes, int n_in,
                              void* d_out, int out_size)
{
    const float* pos = (const float*)d_in[0];
    const float* x   = (const float*)d_in[1];
    const int*   seg = (const int*)  d_in[2];
    const float* W1  = (const float*)d_in[3];
    const float* b1  = (const float*)d_in[4];
    const float* W2  = (const float*)d_in[5];
    const float* b2  = (const float*)d_in[6];
    float* out = (float*)d_out;

    int N = in_sizes[2];               // seg has one entry per node

    // zero g_sum via a graph memset node (cheaper than a 1-block kernel launch)
    void* sum_ptr = nullptr;
    cudaGetSymbolAddress(&sum_ptr, g_sum);
    cudaMemsetAsync(sum_ptr, 0, BP * sizeof(float));

    mlp_exp_sum_kernel<<<(N + 255) / 256, 256>>>(pos, seg, W1, b1, W2, b2,
                                                 out, out_size, N);
    accum_kernel<<<(N + CHUNK - 1) / CHUNK, ATH>>>(x, seg, out, N);
}